// round 3
// baseline (speedup 1.0000x reference)
#include <cuda_runtime.h>
#include <math.h>

#define HW     16384
#define IMG    128
#define TS     8
#define RAD    5
#define KW     11
#define HALO   18
#define NNB    121
#define SSTR   124
#define KSTR   325
#define SCALE  0.11785113019775793f  // 1/sqrt(72)

typedef unsigned long long ull;

__device__ float g_scratch[HW * (72 * 8 + 67)];

__device__ __forceinline__ ull fma2(ull a, ull b, ull c) {
    ull d;
    asm("fma.rn.f32x2 %0, %1, %2, %3;" : "=l"(d) : "l"(a), "l"(b), "l"(c));
    return d;
}
__device__ __forceinline__ ull pack2(float x, float y) {
    ull r;
    asm("mov.b64 %0, {%1, %2};" : "=l"(r) : "f"(x), "f"(y));
    return r;
}
__device__ __forceinline__ float2 unpk2(ull v) {
    float2 r;
    asm("mov.b64 {%0, %1}, %2;" : "=f"(r.x), "=f"(r.y) : "l"(v));
    return r;
}
__device__ __forceinline__ float fsum2(ull v) {
    float2 t = unpk2(v);
    return t.x + t.y;
}
__device__ __forceinline__ float gelu_exact(float x) {
    return 0.5f * x * (1.0f + erff(x * 0.70710678118654752f));
}

union f4u { float4 v; ull u[2]; };

// ---------------------------------------------------------------------------
// MLP: X[p] = [g0+gt (64) | tail (TAIL)], Y = gelu(X @ W + b)
// 64 px / block, 288 thr = 16 pxg(4) x 18 og; outs o = og + 18*j
// ---------------------------------------------------------------------------
template <int TAIL>
__device__ __forceinline__ void mlp_body(const float* __restrict__ g0,
                                         const float* __restrict__ gt,
                                         const float* __restrict__ tail,
                                         const float* __restrict__ W,
                                         const float* __restrict__ B,
                                         float* __restrict__ Y,
                                         int blk, char* smraw) {
    constexpr int DIN  = 64 + TAIL;
    constexpr int DINP = (DIN + 1) & ~1;   // 72 or 68
    constexpr int WSTR = DINP + 2;         // 74 or 70
    float* Xs = (float*)smraw;             // 64*DINP
    float* Ws = Xs + 64 * DINP;            // 72*WSTR
    float* bs = Ws + 72 * WSTR;            // 72
    const int tid = threadIdx.x;
    const int pix0 = blk * 64;

    for (int i = tid; i < 64 * 16; i += 288) {
        int p = i >> 4, c4 = i & 15;
        float4 a = ((const float4*)(g0 + (pix0 + p) * 64))[c4];
        float4 b = ((const float4*)(gt + (pix0 + p) * 64))[c4];
        a.x += b.x; a.y += b.y; a.z += b.z; a.w += b.w;
        *(float4*)&Xs[p * DINP + c4 * 4] = a;
    }
    for (int i = tid; i < 64 * TAIL; i += 288) {
        int p = i / TAIL, c = i - p * TAIL;
        Xs[p * DINP + 64 + c] = tail[(pix0 + p) * TAIL + c];
    }
    if (DINP > DIN)
        for (int i = tid; i < 64; i += 288) Xs[i * DINP + DIN] = 0.f;
    for (int i = tid; i < DIN * 72; i += 288) {
        int k = i / 72, o = i - k * 72;
        Ws[o * WSTR + k] = W[i];
    }
    if (DINP > DIN)
        for (int i = tid; i < 72; i += 288) Ws[i * WSTR + DIN] = 0.f;
    if (tid < 72) bs[tid] = B[tid];
    __syncthreads();

    const int og = tid % 18, pg = tid / 18;
    const int xb = pg * 4;

    ull acc[4][4];
#pragma unroll
    for (int i = 0; i < 4; i++)
#pragma unroll
        for (int j = 0; j < 4; j++) acc[i][j] = 0ULL;

#pragma unroll 2
    for (int kk = 0; kk < DINP; kk += 2) {
        ull x0 = *(const ull*)&Xs[(xb + 0) * DINP + kk];
        ull x1 = *(const ull*)&Xs[(xb + 1) * DINP + kk];
        ull x2 = *(const ull*)&Xs[(xb + 2) * DINP + kk];
        ull x3 = *(const ull*)&Xs[(xb + 3) * DINP + kk];
        ull w0 = *(const ull*)&Ws[(og +  0) * WSTR + kk];
        ull w1 = *(const ull*)&Ws[(og + 18) * WSTR + kk];
        ull w2 = *(const ull*)&Ws[(og + 36) * WSTR + kk];
        ull w3 = *(const ull*)&Ws[(og + 54) * WSTR + kk];
        acc[0][0] = fma2(x0, w0, acc[0][0]); acc[0][1] = fma2(x0, w1, acc[0][1]);
        acc[0][2] = fma2(x0, w2, acc[0][2]); acc[0][3] = fma2(x0, w3, acc[0][3]);
        acc[1][0] = fma2(x1, w0, acc[1][0]); acc[1][1] = fma2(x1, w1, acc[1][1]);
        acc[1][2] = fma2(x1, w2, acc[1][2]); acc[1][3] = fma2(x1, w3, acc[1][3]);
        acc[2][0] = fma2(x2, w0, acc[2][0]); acc[2][1] = fma2(x2, w1, acc[2][1]);
        acc[2][2] = fma2(x2, w2, acc[2][2]); acc[2][3] = fma2(x2, w3, acc[2][3]);
        acc[3][0] = fma2(x3, w0, acc[3][0]); acc[3][1] = fma2(x3, w1, acc[3][1]);
        acc[3][2] = fma2(x3, w2, acc[3][2]); acc[3][3] = fma2(x3, w3, acc[3][3]);
    }
#pragma unroll
    for (int i = 0; i < 4; i++)
#pragma unroll
        for (int j = 0; j < 4; j++) {
            float v = fsum2(acc[i][j]) + bs[og + 18 * j];
            Y[(pix0 + xb + i) * 72 + og + 18 * j] = gelu_exact(v);
        }
}

__global__ __launch_bounds__(288) void mlp_pair_kernel(const float* __restrict__ g0,
                                                       const float* __restrict__ gt,
                                                       const float* __restrict__ pi,
                                                       const float* __restrict__ f,
                                                       const float* __restrict__ W1,
                                                       const float* __restrict__ B1,
                                                       const float* __restrict__ W2,
                                                       const float* __restrict__ B2,
                                                       float* __restrict__ Yq,
                                                       float* __restrict__ Ykv) {
    extern __shared__ char smraw[];
    if (blockIdx.x < 256) mlp_body<8>(g0, gt, pi, W1, B1, Yq,  blockIdx.x, smraw);
    else                  mlp_body<3>(g0, gt, f,  W2, B2, Ykv, blockIdx.x - 256, smraw);
}

// ---------------------------------------------------------------------------
// Dual GEMM: Y1 = X@W1+b1, Y2 = X@W2+b2 (DIN=72)
// ---------------------------------------------------------------------------
__device__ __forceinline__ void dual_body(const float* __restrict__ X,
                                          const float* __restrict__ W1,
                                          const float* __restrict__ B1,
                                          float* __restrict__ Y1,
                                          const float* __restrict__ W2,
                                          const float* __restrict__ B2,
                                          float* __restrict__ Y2,
                                          int blk, char* smraw) {
    float* Xs  = (float*)smraw;        // 64*72
    float* Ws1 = Xs + 64 * 72;         // 72*74
    float* Ws2 = Ws1 + 72 * 74;        // 72*74
    float* bs1 = Ws2 + 72 * 74;
    float* bs2 = bs1 + 72;
    const int tid = threadIdx.x;
    const int pix0 = blk * 64;

    for (int i = tid; i < 64 * 18; i += 288)
        ((float4*)Xs)[i] = ((const float4*)(X + pix0 * 72))[i];
    for (int i = tid; i < 72 * 72; i += 288) {
        int k = i / 72, o = i - k * 72;
        Ws1[o * 74 + k] = W1[i];
        Ws2[o * 74 + k] = W2[i];
    }
    if (tid < 72) { bs1[tid] = B1[tid]; bs2[tid] = B2[tid]; }
    __syncthreads();

    const int og = tid % 18, pg = tid / 18;
    const int xb = pg * 4;

    ull a1[4][4], a2[4][4];
#pragma unroll
    for (int i = 0; i < 4; i++)
#pragma unroll
        for (int j = 0; j < 4; j++) { a1[i][j] = 0ULL; a2[i][j] = 0ULL; }

#pragma unroll 2
    for (int kk = 0; kk < 72; kk += 2) {
        ull x0 = *(const ull*)&Xs[(xb + 0) * 72 + kk];
        ull x1 = *(const ull*)&Xs[(xb + 1) * 72 + kk];
        ull x2 = *(const ull*)&Xs[(xb + 2) * 72 + kk];
        ull x3 = *(const ull*)&Xs[(xb + 3) * 72 + kk];
        ull u0 = *(const ull*)&Ws1[(og +  0) * 74 + kk];
        ull u1 = *(const ull*)&Ws1[(og + 18) * 74 + kk];
        ull u2 = *(const ull*)&Ws1[(og + 36) * 74 + kk];
        ull u3 = *(const ull*)&Ws1[(og + 54) * 74 + kk];
        ull v0 = *(const ull*)&Ws2[(og +  0) * 74 + kk];
        ull v1 = *(const ull*)&Ws2[(og + 18) * 74 + kk];
        ull v2 = *(const ull*)&Ws2[(og + 36) * 74 + kk];
        ull v3 = *(const ull*)&Ws2[(og + 54) * 74 + kk];
        a1[0][0] = fma2(x0, u0, a1[0][0]); a1[0][1] = fma2(x0, u1, a1[0][1]);
        a1[0][2] = fma2(x0, u2, a1[0][2]); a1[0][3] = fma2(x0, u3, a1[0][3]);
        a1[1][0] = fma2(x1, u0, a1[1][0]); a1[1][1] = fma2(x1, u1, a1[1][1]);
        a1[1][2] = fma2(x1, u2, a1[1][2]); a1[1][3] = fma2(x1, u3, a1[1][3]);
        a1[2][0] = fma2(x2, u0, a1[2][0]); a1[2][1] = fma2(x2, u1, a1[2][1]);
        a1[2][2] = fma2(x2, u2, a1[2][2]); a1[2][3] = fma2(x2, u3, a1[2][3]);
        a1[3][0] = fma2(x3, u0, a1[3][0]); a1[3][1] = fma2(x3, u1, a1[3][1]);
        a1[3][2] = fma2(x3, u2, a1[3][2]); a1[3][3] = fma2(x3, u3, a1[3][3]);
        a2[0][0] = fma2(x0, v0, a2[0][0]); a2[0][1] = fma2(x0, v1, a2[0][1]);
        a2[0][2] = fma2(x0, v2, a2[0][2]); a2[0][3] = fma2(x0, v3, a2[0][3]);
        a2[1][0] = fma2(x1, v0, a2[1][0]); a2[1][1] = fma2(x1, v1, a2[1][1]);
        a2[1][2] = fma2(x1, v2, a2[1][2]); a2[1][3] = fma2(x1, v3, a2[1][3]);
        a2[2][0] = fma2(x2, v0, a2[2][0]); a2[2][1] = fma2(x2, v1, a2[2][1]);
        a2[2][2] = fma2(x2, v2, a2[2][2]); a2[2][3] = fma2(x2, v3, a2[2][3]);
        a2[3][0] = fma2(x3, v0, a2[3][0]); a2[3][1] = fma2(x3, v1, a2[3][1]);
        a2[3][2] = fma2(x3, v2, a2[3][2]); a2[3][3] = fma2(x3, v3, a2[3][3]);
    }
#pragma unroll
    for (int i = 0; i < 4; i++)
#pragma unroll
        for (int j = 0; j < 4; j++) {
            int o = og + 18 * j;
            Y1[(pix0 + xb + i) * 72 + o] = fsum2(a1[i][j]) + bs1[o];
            Y2[(pix0 + xb + i) * 72 + o] = fsum2(a2[i][j]) + bs2[o];
        }
}

__global__ __launch_bounds__(288) void dual_kernel(const float* __restrict__ X,
                                                   const float* __restrict__ W1,
                                                   const float* __restrict__ B1,
                                                   float* __restrict__ Y1,
                                                   const float* __restrict__ W2,
                                                   const float* __restrict__ B2,
                                                   float* __restrict__ Y2) {
    extern __shared__ char smraw[];
    dual_body(X, W1, B1, Y1, W2, B2, Y2, blockIdx.x, smraw);
}

__global__ __launch_bounds__(288) void dual_pair_kernel(const float* __restrict__ Xa,
                                                        const float* __restrict__ Wa1,
                                                        const float* __restrict__ Ba1,
                                                        float* __restrict__ Ya1,
                                                        const float* __restrict__ Wa2,
                                                        const float* __restrict__ Ba2,
                                                        float* __restrict__ Ya2,
                                                        const float* __restrict__ Xb,
                                                        const float* __restrict__ Wb1,
                                                        const float* __restrict__ Bb1,
                                                        float* __restrict__ Yb1,
                                                        const float* __restrict__ Wb2,
                                                        const float* __restrict__ Bb2,
                                                        float* __restrict__ Yb2) {
    extern __shared__ char smraw[];
    if (blockIdx.x < 256) dual_body(Xa, Wa1, Ba1, Ya1, Wa2, Ba2, Ya2, blockIdx.x, smraw);
    else                  dual_body(Xb, Wb1, Bb1, Yb1, Wb2, Bb2, Yb2, blockIdx.x - 256, smraw);
}

// ---------------------------------------------------------------------------
// Attention: 8x8 tile, 512 threads. K channel-pair-major (ull), V cell-major.
// ---------------------------------------------------------------------------
__global__ __launch_bounds__(512) void attn_kernel(const float* __restrict__ Q,
                                                   const float* __restrict__ Kp,
                                                   const float* __restrict__ Vp,
                                                   float* __restrict__ O) {
    extern __shared__ char smraw[];
    ull*    Ks2 = (ull*)smraw;                  // 36 * KSTR
    float4* Vs4 = (float4*)(Ks2 + 36 * KSTR);   // 324 * 18
    float*  S   = (float*)(Vs4 + 324 * 18);     // 64 * SSTR
    float*  red = S + 64 * SSTR;                // 64

    const int tid = threadIdx.x;
    const int tx = blockIdx.x, ty = blockIdx.y;
    const int ox = tx * TS - RAD, oy = ty * TS - RAD;

    for (int i = tid; i < HALO * HALO * 18; i += 512) {
        int cell = i / 18, j = i - cell * 18;
        int hy = cell / HALO, hx = cell - hy * HALO;
        int gy = oy + hy, gx = ox + hx;
        f4u kv, vv;
        kv.v = make_float4(0.f, 0.f, 0.f, 0.f);
        vv.v = kv.v;
        if ((unsigned)gy < IMG && (unsigned)gx < IMG) {
            int base = (gy * IMG + gx) * 18;
            kv.v = __ldg((const float4*)Kp + base + j);
            vv.v = __ldg((const float4*)Vp + base + j);
        }
        Vs4[cell * 18 + j] = vv.v;
        Ks2[(2 * j + 0) * KSTR + cell] = kv.u[0];
        Ks2[(2 * j + 1) * KSTR + cell] = kv.u[1];
    }
    __syncthreads();

    const int p = tid >> 3, sub = tid & 7;
    const int py = p >> 3, px = p & 7;
    const int gy = ty * TS + py, gx = tx * TS + px;

    // ---- phase A ----
    {
        ull q2[36];
        const float4* qr = (const float4*)(Q + (gy * IMG + gx) * 72);
#pragma unroll
        for (int jj = 0; jj < 18; jj++) {
            f4u t; t.v = __ldg(qr + jj);
            q2[2 * jj] = t.u[0];
            q2[2 * jj + 1] = t.u[1];
        }
        for (int n = sub; n < NNB; n += 8) {
            int qy = n / 11;
            int qx = n - qy * 11;
            int ny = gy + qy - RAD, nx = gx + qx - RAD;
            float s = -INFINITY;
            if ((unsigned)ny < IMG && (unsigned)nx < IMG) {
                const ull* kc = Ks2 + (py + qy) * HALO + (px + qx);
                ull a0 = 0ULL, a1 = 0ULL, a2 = 0ULL, a3 = 0ULL;
#pragma unroll
                for (int d2 = 0; d2 < 36; d2 += 4) {
                    a0 = fma2(q2[d2 + 0], kc[(d2 + 0) * KSTR], a0);
                    a1 = fma2(q2[d2 + 1], kc[(d2 + 1) * KSTR], a1);
                    a2 = fma2(q2[d2 + 2], kc[(d2 + 2) * KSTR], a2);
                    a3 = fma2(q2[d2 + 3], kc[(d2 + 3) * KSTR], a3);
                }
                s = (fsum2(a0) + fsum2(a1) + fsum2(a2) + fsum2(a3)) * SCALE;
            }
            S[p * SSTR + n] = s;
        }
    }
    __syncwarp();

    // ---- softmax (8-lane cooperative) ----
    {
        float* row = S + p * SSTR;
        float m = -INFINITY;
        for (int n = sub; n < NNB; n += 8) m = fmaxf(m, row[n]);
        m = fmaxf(m, __shfl_xor_sync(0xffffffffu, m, 1));
        m = fmaxf(m, __shfl_xor_sync(0xffffffffu, m, 2));
        m = fmaxf(m, __shfl_xor_sync(0xffffffffu, m, 4));
        float sum = 0.f;
        for (int n = sub; n < NNB; n += 8) {
            float e = __expf(row[n] - m);
            row[n] = e;
            sum += e;
        }
        sum += __shfl_xor_sync(0xffffffffu, sum, 1);
        sum += __shfl_xor_sync(0xffffffffu, sum, 2);
        sum += __shfl_xor_sync(0xffffffffu, sum, 4);
        if (sub == 0) red[p] = 1.0f / sum;
    }
    __syncthreads();

    // ---- phase B ----
    for (int u = tid; u < 64 * 18; u += 512) {
        int pp = u / 18, j = u - pp * 18;
        int ppy = pp >> 3, ppx = pp & 7;
        const float* arow = S + pp * SSTR;
        ull acc01 = 0ULL, acc23 = 0ULL;
#pragma unroll 1
        for (int dy = 0; dy < KW; dy++) {
            const float4* vb = Vs4 + (((ppy + dy) * HALO) + ppx) * 18 + j;
            const float* ar = arow + dy * KW;
#pragma unroll
            for (int dx = 0; dx < KW; dx++) {
                ull aa = pack2(ar[dx], ar[dx]);
                f4u v; v.v = vb[dx * 18];
                acc01 = fma2(aa, v.u[0], acc01);
                acc23 = fma2(aa, v.u[1], acc23);
            }
        }
        float r = red[pp];
        float2 e0 = unpk2(acc01), e1 = unpk2(acc23);
        float4 res = make_float4(e0.x * r, e0.y * r, e1.x * r, e1.y * r);
        int ogy = ty * TS + ppy, ogx = tx * TS + ppx;
        ((float4*)O)[(ogy * IMG + ogx) * 18 + j] = res;
    }
}

// ---------------------------------------------------------------------------
// head (blocks 0..63) + split (blocks 64..)
// ---------------------------------------------------------------------------
__global__ __launch_bounds__(256) void head_split_kernel(const float* __restrict__ gp,
                                                         const float* __restrict__ WG,
                                                         const float* __restrict__ BG,
                                                         const float* __restrict__ WP,
                                                         const float* __restrict__ BP,
                                                         float* __restrict__ out) {
    const int tid = threadIdx.x;
    if (blockIdx.x >= 64) {
        int i = (blockIdx.x - 64) * 256 + tid;
        if (i < HW * 72) {
            int pix = i / 72, c = i - pix * 72;
            float v = gp[i];
            if (c < 64) out[HW * 10 + pix * 64 + c] = v;
            else        out[HW * 74 + pix * 8 + (c - 64)] = v;
        }
        return;
    }
    __shared__ float wg[64 * 7];
    __shared__ float bg[7];
    __shared__ float wp[24];
    __shared__ float bp[3];
    for (int i = tid; i < 448; i += 256) wg[i] = WG[i];
    if (tid < 7)  bg[tid] = BG[tid];
    if (tid < 24) wp[tid] = WP[tid];
    if (tid < 3)  bp[tid] = BP[tid];
    __syncthreads();

    int pix = blockIdx.x * 256 + tid;
    const float* row = gp + pix * 72;

    float gr[7];
#pragma unroll
    for (int j = 0; j < 7; j++) gr[j] = bg[j];
    for (int c = 0; c < 64; c++) {
        float x = row[c];
#pragma unroll
        for (int j = 0; j < 7; j++) gr[j] += x * wg[c * 7 + j];
    }
    float go[7];
#pragma unroll
    for (int j = 0; j < 4; j++) go[j] = 1.0f / (1.0f + __expf(-gr[j]));
    {
        float m = fmaxf(gr[4], fmaxf(gr[5], gr[6]));
        float e0 = __expf(gr[4] - m), e1 = __expf(gr[5] - m), e2 = __expf(gr[6] - m);
        float rs = 1.0f / (e0 + e1 + e2);
        go[4] = e0 * rs; go[5] = e1 * rs; go[6] = e2 * rs;
    }
#pragma unroll
    for (int j = 0; j < 7; j++) out[pix * 7 + j] = go[j];

    float pr[3];
#pragma unroll
    for (int j = 0; j < 3; j++) pr[j] = bp[j];
    for (int c = 0; c < 8; c++) {
        float x = row[64 + c];
#pragma unroll
        for (int j = 0; j < 3; j++) pr[j] += x * wp[c * 3 + j];
    }
    {
        float m = fmaxf(pr[0], fmaxf(pr[1], pr[2]));
        float e0 = __expf(pr[0] - m), e1 = __expf(pr[1] - m), e2 = __expf(pr[2] - m);
        float rs = 1.0f / (e0 + e1 + e2);
        out[HW * 7 + pix * 3 + 0] = e0 * rs;
        out[HW * 7 + pix * 3 + 1] = e1 * rs;
        out[HW * 7 + pix * 3 + 2] = e2 * rs;
    }
}

// ---------------------------------------------------------------------------
extern "C" void kernel_launch(void* const* d_in, const int* in_sizes, int n_in,
                              void* d_out, int out_size) {
    const float* f_t     = (const float*)d_in[0];
    const float* gamma_0 = (const float*)d_in[1];
    const float* gamma_t = (const float*)d_in[2];
    const float* pi_t    = (const float*)d_in[3];
    const float* w_mlp1  = (const float*)d_in[4];
    const float* b_mlp1  = (const float*)d_in[5];
    const float* w_mlp2  = (const float*)d_in[6];
    const float* b_mlp2  = (const float*)d_in[7];
    const float* wq1     = (const float*)d_in[8];
    const float* bq1     = (const float*)d_in[9];
    const float* wk1     = (const float*)d_in[10];
    const float* bk1     = (const float*)d_in[11];
    const float* wv1     = (const float*)d_in[12];
    const float* bv1     = (const float*)d_in[13];
    const float* wq2     = (const float*)d_in[14];
    const float* bq2     = (const float*)d_in[15];
    const float* wk2     = (const float*)d_in[16];
    const float* bk2     = (const float*)d_in[17];
    const float* wv2     = (const float*)d_in[18];
    const float* bv2     = (const float*)d_in[19];
    const float* w_g     = (const float*)d_in[20];
    const float* b_g     = (const float*)d_in[21];
    const float* w_p     = (const float*)d_in[22];
    const float* b_p     = (const float*)d_in[23];
    float* out = (float*)d_out;

    float* base = nullptr;
    cudaGetSymbolAddress((void**)&base, g_scratch);
    float* q   = base;
    float* kv  = q   + HW * 72;
    float* qh1 = kv  + HW * 72;
    float* qh2 = qh1 + HW * 72;
    float* kp  = qh2 + HW * 72;
    float* vp  = kp  + HW * 72;
    float* o1  = vp  + HW * 72;
    float* gp  = o1  + HW * 72;

    const int attn_smem = (36 * KSTR) * 8 + (324 * 18) * 16 + (64 * SSTR + 64) * 4;
    cudaFuncSetAttribute(attn_kernel, cudaFuncAttributeMaxDynamicSharedMemorySize, attn_smem);
    const int dual_smem = (64 * 72 + 2 * 72 * 74 + 144) * (int)sizeof(float);
    cudaFuncSetAttribute(dual_kernel, cudaFuncAttributeMaxDynamicSharedMemorySize, dual_smem);
    cudaFuncSetAttribute(dual_pair_kernel, cudaFuncAttributeMaxDynamicSharedMemorySize, dual_smem);
    const int mlp_smem = (64 * 72 + 72 * 74 + 72) * (int)sizeof(float);

    mlp_pair_kernel<<<512, 288, mlp_smem>>>(gamma_0, gamma_t, pi_t, f_t,
                                            w_mlp1, b_mlp1, w_mlp2, b_mlp2, q, kv);
    dual_pair_kernel<<<512, 288, dual_smem>>>(q,  wq1, bq1, qh1, wq2, bq2, qh2,
                                              kv, wk1, bk1, kp,  wv1, bv1, vp);
    attn_kernel<<<dim3(16, 16), 512, attn_smem>>>(qh1, kp, vp, o1);
    dual_kernel<<<256, 288, dual_smem>>>(o1, wk2, bk2, kp, wv2, bv2, vp);
    attn_kernel<<<dim3(16, 16), 512, attn_smem>>>(qh2, kp, vp, gp);
    head_split_kernel<<<64 + (HW * 72 + 255) / 256, 256>>>(gp, w_g, b_g, w_p, b_p, out);
}

// round 4
// speedup vs baseline: 1.2640x; 1.2640x over previous
#include <cuda_runtime.h>
#include <math.h>

#define HW     16384
#define IMG    128
#define TS     8
#define RAD    5
#define KW     11
#define HALO   18
#define NNB    121
#define SSTR   124
#define KSTR   325
#define SCALE  0.11785113019775793f  // 1/sqrt(72)

typedef unsigned long long ull;

__device__ float g_scratch[HW * (72 * 8 + 67)];

__device__ __forceinline__ float gelu_exact(float x) {
    return 0.5f * x * (1.0f + erff(x * 0.70710678118654752f));
}
// pack two f32 into bf16x2: hi half = a, lo half = b
__device__ __forceinline__ unsigned bf2(float hi, float lo) {
    unsigned r;
    asm("cvt.rn.bf16x2.f32 %0, %1, %2;" : "=r"(r) : "f"(hi), "f"(lo));
    return r;
}
__device__ __forceinline__ float bf_lo(unsigned u) { return __uint_as_float(u << 16); }
__device__ __forceinline__ float bf_hi(unsigned u) { return __uint_as_float(u & 0xffff0000u); }

// ---------------------------------------------------------------------------
// MLP (round-2 scalar body): X = [g0+gt (64) | tail], Y = gelu(X@W + b)
// 64 px / block, 288 thr = 16 pxg(4px) x 18 og(4outs)
// ---------------------------------------------------------------------------
template <int TAIL>
__device__ __forceinline__ void mlp_body(const float* __restrict__ g0,
                                         const float* __restrict__ gt,
                                         const float* __restrict__ tail,
                                         const float* __restrict__ W,
                                         const float* __restrict__ B,
                                         float* __restrict__ Y,
                                         int blk, char* smraw) {
    constexpr int DIN = 64 + TAIL;
    float* Xs = (float*)smraw;        // 64*DIN
    float* Ws = Xs + 64 * DIN;        // DIN*72
    float* bs = Ws + DIN * 72;        // 72
    const int tid = threadIdx.x;
    const int pix0 = blk * 64;

    for (int i = tid; i < 64 * 64; i += 288) {
        int p = i >> 6, c = i & 63;
        Xs[p * DIN + c] = g0[(pix0 + p) * 64 + c] + gt[(pix0 + p) * 64 + c];
    }
    for (int i = tid; i < 64 * TAIL; i += 288) {
        int p = i / TAIL, c = i - p * TAIL;
        Xs[p * DIN + 64 + c] = tail[(pix0 + p) * TAIL + c];
    }
    for (int i = tid; i < DIN * 18; i += 288)
        ((float4*)Ws)[i] = ((const float4*)W)[i];
    if (tid < 72) bs[tid] = B[tid];
    __syncthreads();

    const int og = tid % 18, pg = tid / 18;
    const int ob = og * 4, xb = pg * 4;

    float acc[4][4];
#pragma unroll
    for (int i = 0; i < 4; i++)
#pragma unroll
        for (int j = 0; j < 4; j++) acc[i][j] = 0.0f;

    for (int k = 0; k < DIN; k++) {
        float x0 = Xs[(xb + 0) * DIN + k];
        float x1 = Xs[(xb + 1) * DIN + k];
        float x2 = Xs[(xb + 2) * DIN + k];
        float x3 = Xs[(xb + 3) * DIN + k];
        float4 w = *(const float4*)&Ws[k * 72 + ob];
        acc[0][0] += x0 * w.x; acc[0][1] += x0 * w.y; acc[0][2] += x0 * w.z; acc[0][3] += x0 * w.w;
        acc[1][0] += x1 * w.x; acc[1][1] += x1 * w.y; acc[1][2] += x1 * w.z; acc[1][3] += x1 * w.w;
        acc[2][0] += x2 * w.x; acc[2][1] += x2 * w.y; acc[2][2] += x2 * w.z; acc[2][3] += x2 * w.w;
        acc[3][0] += x3 * w.x; acc[3][1] += x3 * w.y; acc[3][2] += x3 * w.z; acc[3][3] += x3 * w.w;
    }
#pragma unroll
    for (int i = 0; i < 4; i++) {
        float4 r;
        r.x = gelu_exact(acc[i][0] + bs[ob + 0]);
        r.y = gelu_exact(acc[i][1] + bs[ob + 1]);
        r.z = gelu_exact(acc[i][2] + bs[ob + 2]);
        r.w = gelu_exact(acc[i][3] + bs[ob + 3]);
        *(float4*)&Y[(pix0 + xb + i) * 72 + ob] = r;
    }
}

__global__ __launch_bounds__(288) void mlp_pair_kernel(const float* __restrict__ g0,
                                                       const float* __restrict__ gt,
                                                       const float* __restrict__ pi,
                                                       const float* __restrict__ f,
                                                       const float* __restrict__ W1,
                                                       const float* __restrict__ B1,
                                                       const float* __restrict__ W2,
                                                       const float* __restrict__ B2,
                                                       float* __restrict__ Yq,
                                                       float* __restrict__ Ykv) {
    extern __shared__ char smraw[];
    if (blockIdx.x < 256) mlp_body<8>(g0, gt, pi, W1, B1, Yq,  blockIdx.x, smraw);
    else                  mlp_body<3>(g0, gt, f,  W2, B2, Ykv, blockIdx.x - 256, smraw);
}

// ---------------------------------------------------------------------------
// Dual GEMM (round-2 scalar body): Y1 = X@W1+b1, Y2 = X@W2+b2 (DIN=72)
// ---------------------------------------------------------------------------
__device__ __forceinline__ void dual_body(const float* __restrict__ X,
                                          const float* __restrict__ W1,
                                          const float* __restrict__ B1,
                                          float* __restrict__ Y1,
                                          const float* __restrict__ W2,
                                          const float* __restrict__ B2,
                                          float* __restrict__ Y2,
                                          int blk, char* smraw) {
    float* Xs  = (float*)smraw;        // 64*72
    float* Ws1 = Xs + 64 * 72;         // 72*72
    float* Ws2 = Ws1 + 72 * 72;        // 72*72
    float* bs1 = Ws2 + 72 * 72;        // 72
    float* bs2 = bs1 + 72;             // 72

    const int tid = threadIdx.x;
    const int pix0 = blk * 64;

    for (int i = tid; i < 64 * 18; i += 288)
        ((float4*)Xs)[i] = ((const float4*)(X + pix0 * 72))[i];
    for (int i = tid; i < 72 * 18; i += 288) {
        ((float4*)Ws1)[i] = ((const float4*)W1)[i];
        ((float4*)Ws2)[i] = ((const float4*)W2)[i];
    }
    if (tid < 72) { bs1[tid] = B1[tid]; bs2[tid] = B2[tid]; }
    __syncthreads();

    const int og = tid % 18, pg = tid / 18;
    const int ob = og * 4, xb = pg * 4;

    float a1[4][4], a2[4][4];
#pragma unroll
    for (int i = 0; i < 4; i++)
#pragma unroll
        for (int j = 0; j < 4; j++) { a1[i][j] = 0.0f; a2[i][j] = 0.0f; }

    for (int k = 0; k < 72; k++) {
        float x0 = Xs[(xb + 0) * 72 + k];
        float x1 = Xs[(xb + 1) * 72 + k];
        float x2 = Xs[(xb + 2) * 72 + k];
        float x3 = Xs[(xb + 3) * 72 + k];
        float4 w1 = *(const float4*)&Ws1[k * 72 + ob];
        float4 w2 = *(const float4*)&Ws2[k * 72 + ob];
        a1[0][0] += x0 * w1.x; a1[0][1] += x0 * w1.y; a1[0][2] += x0 * w1.z; a1[0][3] += x0 * w1.w;
        a1[1][0] += x1 * w1.x; a1[1][1] += x1 * w1.y; a1[1][2] += x1 * w1.z; a1[1][3] += x1 * w1.w;
        a1[2][0] += x2 * w1.x; a1[2][1] += x2 * w1.y; a1[2][2] += x2 * w1.z; a1[2][3] += x2 * w1.w;
        a1[3][0] += x3 * w1.x; a1[3][1] += x3 * w1.y; a1[3][2] += x3 * w1.z; a1[3][3] += x3 * w1.w;
        a2[0][0] += x0 * w2.x; a2[0][1] += x0 * w2.y; a2[0][2] += x0 * w2.z; a2[0][3] += x0 * w2.w;
        a2[1][0] += x1 * w2.x; a2[1][1] += x1 * w2.y; a2[1][2] += x1 * w2.z; a2[1][3] += x1 * w2.w;
        a2[2][0] += x2 * w2.x; a2[2][1] += x2 * w2.y; a2[2][2] += x2 * w2.z; a2[2][3] += x2 * w2.w;
        a2[3][0] += x3 * w2.x; a2[3][1] += x3 * w2.y; a2[3][2] += x3 * w2.z; a2[3][3] += x3 * w2.w;
    }
#pragma unroll
    for (int i = 0; i < 4; i++) {
        float4 r1, r2;
        r1.x = a1[i][0] + bs1[ob + 0]; r1.y = a1[i][1] + bs1[ob + 1];
        r1.z = a1[i][2] + bs1[ob + 2]; r1.w = a1[i][3] + bs1[ob + 3];
        r2.x = a2[i][0] + bs2[ob + 0]; r2.y = a2[i][1] + bs2[ob + 1];
        r2.z = a2[i][2] + bs2[ob + 2]; r2.w = a2[i][3] + bs2[ob + 3];
        *(float4*)&Y1[(pix0 + xb + i) * 72 + ob] = r1;
        *(float4*)&Y2[(pix0 + xb + i) * 72 + ob] = r2;
    }
}

__global__ __launch_bounds__(288) void dual_kernel(const float* __restrict__ X,
                                                   const float* __restrict__ W1,
                                                   const float* __restrict__ B1,
                                                   float* __restrict__ Y1,
                                                   const float* __restrict__ W2,
                                                   const float* __restrict__ B2,
                                                   float* __restrict__ Y2) {
    extern __shared__ char smraw[];
    dual_body(X, W1, B1, Y1, W2, B2, Y2, blockIdx.x, smraw);
}

__global__ __launch_bounds__(288) void dual_pair_kernel(const float* __restrict__ Xa,
                                                        const float* __restrict__ Wa1,
                                                        const float* __restrict__ Ba1,
                                                        float* __restrict__ Ya1,
                                                        const float* __restrict__ Wa2,
                                                        const float* __restrict__ Ba2,
                                                        float* __restrict__ Ya2,
                                                        const float* __restrict__ Xb,
                                                        const float* __restrict__ Wb1,
                                                        const float* __restrict__ Bb1,
                                                        float* __restrict__ Yb1,
                                                        const float* __restrict__ Wb2,
                                                        const float* __restrict__ Bb2,
                                                        float* __restrict__ Yb2) {
    extern __shared__ char smraw[];
    if (blockIdx.x < 256) dual_body(Xa, Wa1, Ba1, Ya1, Wa2, Ba2, Ya2, blockIdx.x, smraw);
    else                  dual_body(Xb, Wb1, Bb1, Yb1, Wb2, Bb2, Yb2, blockIdx.x - 256, smraw);
}

// ---------------------------------------------------------------------------
// Attention: 8x8 tile, 512 threads. K bf16 channel-pair-major; V bf16x4
// cell-major; scores fp32; all arithmetic fp32 (bf16 unpack = shift/mask).
// ---------------------------------------------------------------------------
__global__ __launch_bounds__(512) void attn_kernel(const float* __restrict__ Q,
                                                   const float* __restrict__ Kp,
                                                   const float* __restrict__ Vp,
                                                   float* __restrict__ O) {
    extern __shared__ char smraw[];
    unsigned* Ksh = (unsigned*)smraw;            // 36 * KSTR  (bf16x2 per entry)
    ull*      Vsh = (ull*)(Ksh + 36 * KSTR);     // 324 * 18   (bf16x4 per entry)
    float*    S   = (float*)(Vsh + 324 * 18);    // 64 * SSTR
    float*    red = S + 64 * SSTR;               // 64

    const int tid = threadIdx.x;
    const int tx = blockIdx.x, ty = blockIdx.y;
    const int ox = tx * TS - RAD, oy = ty * TS - RAD;

    // halo load + fp32 -> bf16 conversion
    for (int i = tid; i < HALO * HALO * 18; i += 512) {
        int cell = i / 18, j = i - cell * 18;
        int hy = cell / HALO, hx = cell - hy * HALO;
        int gy = oy + hy, gx = ox + hx;
        float4 kv = make_float4(0.f, 0.f, 0.f, 0.f);
        float4 vv = kv;
        if ((unsigned)gy < IMG && (unsigned)gx < IMG) {
            int base = (gy * IMG + gx) * 18;
            kv = __ldg((const float4*)Kp + base + j);
            vv = __ldg((const float4*)Vp + base + j);
        }
        Ksh[(2 * j + 0) * KSTR + cell] = bf2(kv.y, kv.x);
        Ksh[(2 * j + 1) * KSTR + cell] = bf2(kv.w, kv.z);
        unsigned v01 = bf2(vv.y, vv.x);
        unsigned v23 = bf2(vv.w, vv.z);
        Vsh[cell * 18 + j] = ((ull)v23 << 32) | (ull)v01;
    }
    __syncthreads();

    const int p = tid >> 3, sub = tid & 7;
    const int py = p >> 3, px = p & 7;
    const int gy = ty * TS + py, gx = tx * TS + px;

    // ---- phase A: scores ----
    {
        float q[72];
        const float4* qr = (const float4*)(Q + (gy * IMG + gx) * 72);
#pragma unroll
        for (int jj = 0; jj < 18; jj++) {
            float4 t = __ldg(qr + jj);
            q[4 * jj + 0] = t.x; q[4 * jj + 1] = t.y;
            q[4 * jj + 2] = t.z; q[4 * jj + 3] = t.w;
        }
        for (int n = sub; n < NNB; n += 8) {
            int qy = n / 11;
            int qx = n - qy * 11;
            int ny = gy + qy - RAD, nx = gx + qx - RAD;
            float s = -INFINITY;
            if ((unsigned)ny < IMG && (unsigned)nx < IMG) {
                const unsigned* kc = Ksh + (py + qy) * HALO + (px + qx);
                float a0 = 0.f, a1 = 0.f, a2 = 0.f, a3 = 0.f;
#pragma unroll
                for (int j2 = 0; j2 < 36; j2 += 2) {
                    unsigned u0 = kc[(j2 + 0) * KSTR];
                    unsigned u1 = kc[(j2 + 1) * KSTR];
                    a0 = fmaf(q[2 * j2 + 0], bf_lo(u0), a0);
                    a1 = fmaf(q[2 * j2 + 1], bf_hi(u0), a1);
                    a2 = fmaf(q[2 * j2 + 2], bf_lo(u1), a2);
                    a3 = fmaf(q[2 * j2 + 3], bf_hi(u1), a3);
                }
                s = (a0 + a1 + a2 + a3) * SCALE;
            }
            S[p * SSTR + n] = s;
        }
    }
    __syncwarp();

    // ---- softmax: 8-lane cooperative ----
    {
        float* row = S + p * SSTR;
        float m = -INFINITY;
        for (int n = sub; n < NNB; n += 8) m = fmaxf(m, row[n]);
        m = fmaxf(m, __shfl_xor_sync(0xffffffffu, m, 1));
        m = fmaxf(m, __shfl_xor_sync(0xffffffffu, m, 2));
        m = fmaxf(m, __shfl_xor_sync(0xffffffffu, m, 4));
        float sum = 0.f;
        for (int n = sub; n < NNB; n += 8) {
            float e = __expf(row[n] - m);
            row[n] = e;
            sum += e;
        }
        sum += __shfl_xor_sync(0xffffffffu, sum, 1);
        sum += __shfl_xor_sync(0xffffffffu, sum, 2);
        sum += __shfl_xor_sync(0xffffffffu, sum, 4);
        if (sub == 0) red[p] = 1.0f / sum;
    }
    __syncthreads();

    // ---- phase B: attn @ V ----
    for (int u = tid; u < 64 * 18; u += 512) {
        int pp = u / 18, j = u - pp * 18;
        int ppy = pp >> 3, ppx = pp & 7;
        const float* arow = S + pp * SSTR;
        float c0 = 0.f, c1 = 0.f, c2 = 0.f, c3 = 0.f;
#pragma unroll 1
        for (int dy = 0; dy < KW; dy++) {
            const ull* vb = Vsh + (((ppy + dy) * HALO) + ppx) * 18 + j;
            const float* ar = arow + dy * KW;
#pragma unroll
            for (int dx = 0; dx < KW; dx++) {
                float a = ar[dx];
                ull v = vb[dx * 18];
                unsigned u0 = (unsigned)v;
                unsigned u1 = (unsigned)(v >> 32);
                c0 = fmaf(a, bf_lo(u0), c0);
                c1 = fmaf(a, bf_hi(u0), c1);
                c2 = fmaf(a, bf_lo(u1), c2);
                c3 = fmaf(a, bf_hi(u1), c3);
            }
        }
        float r = red[pp];
        float4 res = make_float4(c0 * r, c1 * r, c2 * r, c3 * r);
        int ogy = ty * TS + ppy, ogx = tx * TS + ppx;
        ((float4*)O)[(ogy * IMG + ogx) * 18 + j] = res;
    }
}

// ---------------------------------------------------------------------------
// head (blocks 0..63) + split (blocks 64..)
// ---------------------------------------------------------------------------
__global__ __launch_bounds__(256) void head_split_kernel(const float* __restrict__ gp,
                                                         const float* __restrict__ WG,
                                                         const float* __restrict__ BG,
                                                         const float* __restrict__ WP,
                                                         const float* __restrict__ BP,
                                                         float* __restrict__ out) {
    const int tid = threadIdx.x;
    if (blockIdx.x >= 64) {
        int i = (blockIdx.x - 64) * 256 + tid;
        if (i < HW * 72) {
            int pix = i / 72, c = i - pix * 72;
            float v = gp[i];
            if (c < 64) out[HW * 10 + pix * 64 + c] = v;
            else        out[HW * 74 + pix * 8 + (c - 64)] = v;
        }
        return;
    }
    __shared__ float wg[64 * 7];
    __shared__ float bg[7];
    __shared__ float wp[24];
    __shared__ float bp[3];
    for (int i = tid; i < 448; i += 256) wg[i] = WG[i];
    if (tid < 7)  bg[tid] = BG[tid];
    if (tid < 24) wp[tid] = WP[tid];
    if (tid < 3)  bp[tid] = BP[tid];
    __syncthreads();

    int pix = blockIdx.x * 256 + tid;
    const float* row = gp + pix * 72;

    float gr[7];
#pragma unroll
    for (int j = 0; j < 7; j++) gr[j] = bg[j];
    for (int c = 0; c < 64; c++) {
        float x = row[c];
#pragma unroll
        for (int j = 0; j < 7; j++) gr[j] += x * wg[c * 7 + j];
    }
    float go[7];
#pragma unroll
    for (int j = 0; j < 4; j++) go[j] = 1.0f / (1.0f + __expf(-gr[j]));
    {
        float m = fmaxf(gr[4], fmaxf(gr[5], gr[6]));
        float e0 = __expf(gr[4] - m), e1 = __expf(gr[5] - m), e2 = __expf(gr[6] - m);
        float rs = 1.0f / (e0 + e1 + e2);
        go[4] = e0 * rs; go[5] = e1 * rs; go[6] = e2 * rs;
    }
#pragma unroll
    for (int j = 0; j < 7; j++) out[pix * 7 + j] = go[j];

    float pr[3];
#pragma unroll
    for (int j = 0; j < 3; j++) pr[j] = bp[j];
    for (int c = 0; c < 8; c++) {
        float x = row[64 + c];
#pragma unroll
        for (int j = 0; j < 3; j++) pr[j] += x * wp[c * 3 + j];
    }
    {
        float m = fmaxf(pr[0], fmaxf(pr[1], pr[2]));
        float e0 = __expf(pr[0] - m), e1 = __expf(pr[1] - m), e2 = __expf(pr[2] - m);
        float rs = 1.0f / (e0 + e1 + e2);
        out[HW * 7 + pix * 3 + 0] = e0 * rs;
        out[HW * 7 + pix * 3 + 1] = e1 * rs;
        out[HW * 7 + pix * 3 + 2] = e2 * rs;
    }
}

// ---------------------------------------------------------------------------
extern "C" void kernel_launch(void* const* d_in, const int* in_sizes, int n_in,
                              void* d_out, int out_size) {
    const float* f_t     = (const float*)d_in[0];
    const float* gamma_0 = (const float*)d_in[1];
    const float* gamma_t = (const float*)d_in[2];
    const float* pi_t    = (const float*)d_in[3];
    const float* w_mlp1  = (const float*)d_in[4];
    const float* b_mlp1  = (const float*)d_in[5];
    const float* w_mlp2  = (const float*)d_in[6];
    const float* b_mlp2  = (const float*)d_in[7];
    const float* wq1     = (const float*)d_in[8];
    const float* bq1     = (const float*)d_in[9];
    const float* wk1     = (const float*)d_in[10];
    const float* bk1     = (const float*)d_in[11];
    const float* wv1     = (const float*)d_in[12];
    const float* bv1     = (const float*)d_in[13];
    const float* wq2     = (const float*)d_in[14];
    const float* bq2     = (const float*)d_in[15];
    const float* wk2     = (const float*)d_in[16];
    const float* bk2     = (const float*)d_in[17];
    const float* wv2     = (const float*)d_in[18];
    const float* bv2     = (const float*)d_in[19];
    const float* w_g     = (const float*)d_in[20];
    const float* b_g     = (const float*)d_in[21];
    const float* w_p     = (const float*)d_in[22];
    const float* b_p     = (const float*)d_in[23];
    float* out = (float*)d_out;

    float* base = nullptr;
    cudaGetSymbolAddress((void**)&base, g_scratch);
    float* q   = base;
    float* kv  = q   + HW * 72;
    float* qh1 = kv  + HW * 72;
    float* qh2 = qh1 + HW * 72;
    float* kp  = qh2 + HW * 72;
    float* vp  = kp  + HW * 72;
    float* o1  = vp  + HW * 72;
    float* gp  = o1  + HW * 72;

    const int attn_smem = (36 * KSTR) * 4 + (324 * 18) * 8 + (64 * SSTR + 64) * 4;
    cudaFuncSetAttribute(attn_kernel, cudaFuncAttributeMaxDynamicSharedMemorySize, attn_smem);
    const int dual_smem = (64 * 72 + 2 * 72 * 72 + 144) * (int)sizeof(float);
    cudaFuncSetAttribute(dual_kernel, cudaFuncAttributeMaxDynamicSharedMemorySize, dual_smem);
    cudaFuncSetAttribute(dual_pair_kernel, cudaFuncAttributeMaxDynamicSharedMemorySize, dual_smem);
    const int mlp_smem = (64 * 72 + 72 * 72 + 72) * (int)sizeof(float);

    mlp_pair_kernel<<<512, 288, mlp_smem>>>(gamma_0, gamma_t, pi_t, f_t,
                                            w_mlp1, b_mlp1, w_mlp2, b_mlp2, q, kv);
    dual_pair_kernel<<<512, 288, dual_smem>>>(q,  wq1, bq1, qh1, wq2, bq2, qh2,
                                              kv, wk1, bk1, kp,  wv1, bv1, vp);
    attn_kernel<<<dim3(16, 16), 512, attn_smem>>>(qh1, kp, vp, o1);
    dual_kernel<<<256, 288, dual_smem>>>(o1, wk2, bk2, kp, wv2, bv2, vp);
    attn_kernel<<<dim3(16, 16), 512, attn_smem>>>(qh2, kp, vp, gp);
    head_split_kernel<<<64 + (HW * 72 + 255) / 256, 256>>>(gp, w_g, b_g, w_p, b_p, out);
}